// round 15
// baseline (speedup 1.0000x reference)
#include <cuda_runtime.h>
#include <cstddef>

typedef unsigned long long u64;

#define T_LEN 4096
#define KW    15
#define PAD   7
#define TILE  256
#define RPT   16          // t-values per thread
#define LANES 16          // TILE / RPT
#define NTHR  128         // 8 out-channels * 16 lane-slots
#define XROW  286         // swizzled row length: swz(269)=285 -> 286
#define B_SZ  16

// Scratch (alloc-guard-safe): ping-pong intermediates.
__device__ float g_bufA[(size_t)16 * 512 * 4096];   // 134 MB
__device__ float g_bufB[(size_t)16 * 256 * 4096];   //  67 MB

__device__ __forceinline__ u64 pack2(float x, float y) {
    u64 u; asm("mov.b64 %0, {%1, %2};" : "=l"(u) : "f"(x), "f"(y)); return u;
}
__device__ __forceinline__ void unpack2(u64 u, float& x, float& y) {
    asm("mov.b64 {%0, %1}, %2;" : "=f"(x), "=f"(y) : "l"(u));
}
// Packed dual-FP32 FMA (sm_100+): d = a*b + c on both 32-bit halves.
__device__ __forceinline__ u64 ffma2(u64 a, u64 b, u64 c) {
    u64 d; asm("fma.rn.f32x2 %0, %1, %2, %3;" : "=l"(d) : "l"(a), "l"(b), "l"(c));
    return d;
}
__device__ __forceinline__ float lrelu(float v) { return v > 0.f ? v : 0.01f * v; }

// Grouped 1D conv, K=15, SAME, leaky-ReLU epilogue.
// Block = (t-tile of 256) x (one group) x (one batch PAIR).
// f32x2 lanes carry batches (b0,b1).  cin0 channels come from in0 at group
// base g*cin0; the remaining CIN-cin0 channels come from in1 at channel
// in1_chbase + g*(CIN-cin0) (used only by the 'br' concat layer).
template<int CIN>
__global__ void __launch_bounds__(NTHR, 4)
gconv_kernel(const float* __restrict__ in0, int in0_nch, int cin0,
             const float* __restrict__ in1, int in1_nch, int in1_chbase,
             const float* __restrict__ W, const float* __restrict__ bias,
             float* __restrict__ out, int out_nch)
{
    extern __shared__ u64 smem[];
    u64* xs  = smem;                 // [CIN][XROW] skewed {b0,b1} pairs
    u64* wsh = smem + CIN * XROW;    // [8][CIN][KW] duplicated {w,w} pairs

    const int tid    = threadIdx.x;
    const int g      = blockIdx.y;
    const int tstart = blockIdx.x * TILE;
    const int b0     = blockIdx.z * 2, b1 = b0 + 1;
    const int cin1   = CIN - cin0;

    // ---- stage input tile (with halo) into skewed shared memory ----
    for (int ci = 0; ci < CIN; ++ci) {
        const float *s0, *s1;
        if (ci < cin0) {
            size_t ch = (size_t)g * cin0 + ci;
            s0 = in0 + ((size_t)b0 * in0_nch + ch) * T_LEN;
            s1 = in0 + ((size_t)b1 * in0_nch + ch) * T_LEN;
        } else {
            size_t ch = (size_t)in1_chbase + (size_t)g * cin1 + (ci - cin0);
            s0 = in1 + ((size_t)b0 * in1_nch + ch) * T_LEN;
            s1 = in1 + ((size_t)b1 * in1_nch + ch) * T_LEN;
        }
        for (int tt = tid; tt < TILE + KW - 1; tt += NTHR) {
            int t = tstart - PAD + tt;
            float vx = 0.f, vy = 0.f;
            if ((unsigned)t < (unsigned)T_LEN) { vx = s0[t]; vy = s1[t]; }
            // additive skew: conflict-free LDS.64 for lane stride of 16 pairs
            xs[ci * XROW + tt + (tt >> 4)] = pack2(vx, vy);
        }
    }
    // ---- stage this group's weights as duplicated pairs ----
    {
        const float* Wg = W + (size_t)g * 8 * CIN * KW;
        for (int i = tid; i < 8 * CIN * KW; i += NTHR) {
            float w = Wg[i];
            wsh[i] = pack2(w, w);
        }
    }
    __syncthreads();

    const int l  = tid & (LANES - 1);   // t-slot
    const int co = tid >> 4;            // out channel within group
    const int oc = g * 8 + co;

    const float bv = bias[oc];
    const u64 bb = pack2(bv, bv);
    u64 acc[RPT];
    #pragma unroll
    for (int r = 0; r < RPT; ++r) acc[r] = bb;

    const u64* xbase = xs + 17 * l;           // swz(16*l + j) = 17*l + j + (j>>4)
    const u64* wbase = wsh + co * CIN * KW;

    #pragma unroll 1
    for (int ci = 0; ci < CIN; ++ci) {
        const u64* xr = xbase + ci * XROW;
        u64 xv[RPT + KW - 1];                 // 30 pairs, register-resident
        #pragma unroll
        for (int j = 0; j < RPT + KW - 1; ++j) xv[j] = xr[j + (j >> 4)];
        const u64* wr = wbase + ci * KW;
        #pragma unroll
        for (int k = 0; k < KW; ++k) {
            u64 wk = wr[k];
            #pragma unroll
            for (int r = 0; r < RPT; ++r)
                acc[r] = ffma2(wk, xv[r + k], acc[r]);
        }
    }

    // ---- epilogue: leaky ReLU, unpack batch pair, vectorized store ----
    float* o0 = out + ((size_t)b0 * out_nch + oc) * T_LEN + tstart + l * RPT;
    float* o1 = out + ((size_t)b1 * out_nch + oc) * T_LEN + tstart + l * RPT;
    #pragma unroll
    for (int r4 = 0; r4 < RPT; r4 += 4) {
        float4 v0, v1; float a, b;
        unpack2(acc[r4 + 0], a, b); v0.x = lrelu(a); v1.x = lrelu(b);
        unpack2(acc[r4 + 1], a, b); v0.y = lrelu(a); v1.y = lrelu(b);
        unpack2(acc[r4 + 2], a, b); v0.z = lrelu(a); v1.z = lrelu(b);
        unpack2(acc[r4 + 3], a, b); v0.w = lrelu(a); v1.w = lrelu(b);
        *reinterpret_cast<float4*>(o0 + r4) = v0;
        *reinterpret_cast<float4*>(o1 + r4) = v1;
    }
}

// Root: 1x1 conv over 16 channels, no activation.
__global__ void root_kernel(const float* __restrict__ h,
                            const float* __restrict__ Wr,
                            const float* __restrict__ brt,
                            float* __restrict__ out)
{
    int idx = blockIdx.x * blockDim.x + threadIdx.x;   // B * T/4 threads
    if (idx >= B_SZ * (T_LEN / 4)) return;
    int b  = idx >> 10;            // T/4 = 1024
    int t4 = (idx & 1023) * 4;
    const float* hb = h + (size_t)b * 16 * T_LEN + t4;
    float bias = brt[0];
    float4 s = make_float4(bias, bias, bias, bias);
    #pragma unroll
    for (int c = 0; c < 16; ++c) {
        float w = Wr[c];
        float4 v = *reinterpret_cast<const float4*>(hb + (size_t)c * T_LEN);
        s.x += w * v.x; s.y += w * v.y; s.z += w * v.z; s.w += w * v.w;
    }
    *reinterpret_cast<float4*>(out + (size_t)b * T_LEN + t4) = s;
}

extern "C" void kernel_launch(void* const* d_in, const int* in_sizes, int n_in,
                              void* d_out, int out_size)
{
    const float* x      = (const float*)d_in[0];
    const float* W_leaf = (const float*)d_in[1];
    const float* b_leaf = (const float*)d_in[2];
    const float* W_int0 = (const float*)d_in[3];
    const float* b_int0 = (const float*)d_in[4];
    const float* W_br   = (const float*)d_in[5];
    const float* b_br   = (const float*)d_in[6];
    const float* W_int1 = (const float*)d_in[7];
    const float* b_int1 = (const float*)d_in[8];
    const float* W_int2 = (const float*)d_in[9];
    const float* b_int2 = (const float*)d_in[10];
    const float* W_int3 = (const float*)d_in[11];
    const float* b_int3 = (const float*)d_in[12];
    const float* W_int4 = (const float*)d_in[13];
    const float* b_int4 = (const float*)d_in[14];
    const float* W_root = (const float*)d_in[15];
    const float* b_root = (const float*)d_in[16];

    float *bufA = nullptr, *bufB = nullptr;
    cudaGetSymbolAddress((void**)&bufA, g_bufA);
    cudaGetSymbolAddress((void**)&bufB, g_bufB);

    const int SM20 = 20 * (XROW + 8 * KW) * 8;   // 20*(286+120)*8 = 64960 B
    const int SM16 = 16 * (XROW + 8 * KW) * 8;   // 51968 B
    cudaFuncSetAttribute(gconv_kernel<20>,
                         cudaFuncAttributeMaxDynamicSharedMemorySize, SM20);
    cudaFuncSetAttribute(gconv_kernel<16>,
                         cudaFuncAttributeMaxDynamicSharedMemorySize, SM16);

    dim3 blk(NTHR);
    const int GT = T_LEN / TILE;   // 16 t-tiles
    const int BP = B_SZ / 2;       // 8 batch pairs

    // leaf: x[0:1280] -> bufA (512 ch)
    gconv_kernel<20><<<dim3(GT, 64, BP), blk, SM20>>>(
        x, 1536, 20, x, 0, 0, W_leaf, b_leaf, bufA, 512);
    // int0: bufA (512) -> bufB (256)
    gconv_kernel<16><<<dim3(GT, 32, BP), blk, SM16>>>(
        bufA, 512, 16, x, 0, 0, W_int0, b_int0, bufB, 256);
    // br: concat(bufB group 8ch, x[1280+g*8 .. +8]) -> bufA (256)
    gconv_kernel<16><<<dim3(GT, 32, BP), blk, SM16>>>(
        bufB, 256, 8, x, 1536, 1280, W_br, b_br, bufA, 256);
    // int1: bufA (256) -> bufB (128)
    gconv_kernel<16><<<dim3(GT, 16, BP), blk, SM16>>>(
        bufA, 256, 16, x, 0, 0, W_int1, b_int1, bufB, 128);
    // int2: bufB (128) -> bufA (64)
    gconv_kernel<16><<<dim3(GT, 8, BP), blk, SM16>>>(
        bufB, 128, 16, x, 0, 0, W_int2, b_int2, bufA, 64);
    // int3: bufA (64) -> bufB (32)
    gconv_kernel<16><<<dim3(GT, 4, BP), blk, SM16>>>(
        bufA, 64, 16, x, 0, 0, W_int3, b_int3, bufB, 32);
    // int4: bufB (32) -> bufA (16)
    gconv_kernel<16><<<dim3(GT, 2, BP), blk, SM16>>>(
        bufB, 32, 16, x, 0, 0, W_int4, b_int4, bufA, 16);
    // root: bufA (16) -> out
    root_kernel<<<(B_SZ * (T_LEN / 4) + 255) / 256, 256>>>(
        bufA, W_root, b_root, (float*)d_out);
}

// round 16
// speedup vs baseline: 1.1698x; 1.1698x over previous
#include <cuda_runtime.h>
#include <cstddef>

typedef unsigned long long u64;

#define T_LEN 4096
#define KW    15
#define PAD   7
#define TILE  256
#define RPT   16          // t-values per thread
#define LANES 16          // TILE / RPT
#define NTHR  128         // 8 out-channels * 16 lane-slots
#define XROW  286         // skewed row length: skew(269)=285 -> 286
#define B_SZ  16

// Scratch (alloc-guard-safe): ping-pong intermediates.
__device__ float g_bufA[(size_t)16 * 512 * 4096];   // 134 MB
__device__ float g_bufB[(size_t)16 * 256 * 4096];   //  67 MB

__device__ __forceinline__ u64 pack2(float x, float y) {
    u64 u; asm("mov.b64 %0, {%1, %2};" : "=l"(u) : "f"(x), "f"(y)); return u;
}
__device__ __forceinline__ void unpack2(u64 u, float& x, float& y) {
    asm("mov.b64 {%0, %1}, %2;" : "=f"(x), "=f"(y) : "l"(u));
}
// Packed dual-FP32 FMA (sm_100+): d = a*b + c on both 32-bit halves.
__device__ __forceinline__ u64 ffma2(u64 a, u64 b, u64 c) {
    u64 d; asm("fma.rn.f32x2 %0, %1, %2, %3;" : "=l"(d) : "l"(a), "l"(b), "l"(c));
    return d;
}
__device__ __forceinline__ float lrelu(float v) { return v > 0.f ? v : 0.01f * v; }

// Grouped 1D conv, K=15, SAME, leaky-ReLU epilogue.
// Block = (t-tile of 256) x (one group) x (one batch PAIR).
// f32x2 lanes carry batches (b0,b1).  cin0 channels come from in0 at group
// base g*cin0; the remaining CIN-cin0 channels come from in1 at channel
// in1_chbase + g*(CIN-cin0) (used only by the 'br' concat layer).
template<int CIN>
__global__ void __launch_bounds__(NTHR)
gconv_kernel(const float* __restrict__ in0, int in0_nch, int cin0,
             const float* __restrict__ in1, int in1_nch, int in1_chbase,
             const float* __restrict__ W, const float* __restrict__ bias,
             float* __restrict__ out, int out_nch)
{
    extern __shared__ u64 smem[];
    u64*   xs  = smem;                           // [CIN][XROW] skewed {b0,b1} pairs
    float* wsh = (float*)(smem + CIN * XROW);    // [8][CIN][KW] plain f32

    const int tid    = threadIdx.x;
    const int g      = blockIdx.y;
    const int tstart = blockIdx.x * TILE;
    const int b0     = blockIdx.z * 2, b1 = b0 + 1;
    const int cin1   = CIN - cin0;

    // ---- stage input tile (with halo) into skewed shared memory ----
    for (int ci = 0; ci < CIN; ++ci) {
        const float *s0, *s1;
        if (ci < cin0) {
            size_t ch = (size_t)g * cin0 + ci;
            s0 = in0 + ((size_t)b0 * in0_nch + ch) * T_LEN;
            s1 = in0 + ((size_t)b1 * in0_nch + ch) * T_LEN;
        } else {
            size_t ch = (size_t)in1_chbase + (size_t)g * cin1 + (ci - cin0);
            s0 = in1 + ((size_t)b0 * in1_nch + ch) * T_LEN;
            s1 = in1 + ((size_t)b1 * in1_nch + ch) * T_LEN;
        }
        for (int tt = tid; tt < TILE + KW - 1; tt += NTHR) {
            int t = tstart - PAD + tt;
            float vx = 0.f, vy = 0.f;
            if ((unsigned)t < (unsigned)T_LEN) { vx = s0[t]; vy = s1[t]; }
            // additive skew: conflict-free LDS.64 for lane stride of 16 pairs
            xs[ci * XROW + tt + (tt >> 4)] = pack2(vx, vy);
        }
    }
    // ---- stage this group's weights (plain f32, packed at use) ----
    {
        const float* Wg = W + (size_t)g * 8 * CIN * KW;
        for (int i = tid; i < 8 * CIN * KW; i += NTHR)
            wsh[i] = Wg[i];
    }
    __syncthreads();

    const int l  = tid & (LANES - 1);   // t-slot
    const int co = tid >> 4;            // out channel within group
    const int oc = g * 8 + co;

    const float bv = bias[oc];
    const u64 bb = pack2(bv, bv);
    u64 acc[RPT];
    #pragma unroll
    for (int r = 0; r < RPT; ++r) acc[r] = bb;

    const u64*   xbase = xs + 17 * l;        // skew(16*l + j) = 17*l + j + (j>>4)
    const float* wbase = wsh + co * CIN * KW;

    #pragma unroll 1
    for (int ci = 0; ci < CIN; ++ci) {
        const u64* xr = xbase + ci * XROW;
        u64 xv[RPT + KW - 1];                 // 30 pairs, register-resident
        #pragma unroll
        for (int j = 0; j < RPT + KW - 1; ++j) xv[j] = xr[j + (j >> 4)];
        const float* wr = wbase + ci * KW;
        #pragma unroll
        for (int k = 0; k < KW; ++k) {
            float w = wr[k];                  // broadcast LDS.32
            u64 wk = pack2(w, w);             // 1 MOV, off the fma pipe
            #pragma unroll
            for (int r = 0; r < RPT; ++r)
                acc[r] = ffma2(wk, xv[r + k], acc[r]);
        }
    }

    // ---- epilogue: leaky ReLU, unpack batch pair, vectorized store ----
    float* o0 = out + ((size_t)b0 * out_nch + oc) * T_LEN + tstart + l * RPT;
    float* o1 = out + ((size_t)b1 * out_nch + oc) * T_LEN + tstart + l * RPT;
    #pragma unroll
    for (int r4 = 0; r4 < RPT; r4 += 4) {
        float4 v0, v1; float a, b;
        unpack2(acc[r4 + 0], a, b); v0.x = lrelu(a); v1.x = lrelu(b);
        unpack2(acc[r4 + 1], a, b); v0.y = lrelu(a); v1.y = lrelu(b);
        unpack2(acc[r4 + 2], a, b); v0.z = lrelu(a); v1.z = lrelu(b);
        unpack2(acc[r4 + 3], a, b); v0.w = lrelu(a); v1.w = lrelu(b);
        *reinterpret_cast<float4*>(o0 + r4) = v0;
        *reinterpret_cast<float4*>(o1 + r4) = v1;
    }
}

// Root: 1x1 conv over 16 channels, no activation.
__global__ void root_kernel(const float* __restrict__ h,
                            const float* __restrict__ Wr,
                            const float* __restrict__ brt,
                            float* __restrict__ out)
{
    int idx = blockIdx.x * blockDim.x + threadIdx.x;   // B * T/4 threads
    if (idx >= B_SZ * (T_LEN / 4)) return;
    int b  = idx >> 10;            // T/4 = 1024
    int t4 = (idx & 1023) * 4;
    const float* hb = h + (size_t)b * 16 * T_LEN + t4;
    float bias = brt[0];
    float4 s = make_float4(bias, bias, bias, bias);
    #pragma unroll
    for (int c = 0; c < 16; ++c) {
        float w = Wr[c];
        float4 v = *reinterpret_cast<const float4*>(hb + (size_t)c * T_LEN);
        s.x += w * v.x; s.y += w * v.y; s.z += w * v.z; s.w += w * v.w;
    }
    *reinterpret_cast<float4*>(out + (size_t)b * T_LEN + t4) = s;
}

extern "C" void kernel_launch(void* const* d_in, const int* in_sizes, int n_in,
                              void* d_out, int out_size)
{
    const float* x      = (const float*)d_in[0];
    const float* W_leaf = (const float*)d_in[1];
    const float* b_leaf = (const float*)d_in[2];
    const float* W_int0 = (const float*)d_in[3];
    const float* b_int0 = (const float*)d_in[4];
    const float* W_br   = (const float*)d_in[5];
    const float* b_br   = (const float*)d_in[6];
    const float* W_int1 = (const float*)d_in[7];
    const float* b_int1 = (const float*)d_in[8];
    const float* W_int2 = (const float*)d_in[9];
    const float* b_int2 = (const float*)d_in[10];
    const float* W_int3 = (const float*)d_in[11];
    const float* b_int3 = (const float*)d_in[12];
    const float* W_int4 = (const float*)d_in[13];
    const float* b_int4 = (const float*)d_in[14];
    const float* W_root = (const float*)d_in[15];
    const float* b_root = (const float*)d_in[16];

    float *bufA = nullptr, *bufB = nullptr;
    cudaGetSymbolAddress((void**)&bufA, g_bufA);
    cudaGetSymbolAddress((void**)&bufB, g_bufB);

    const int SM20 = 20 * XROW * 8 + 20 * 8 * KW * 4;   // 45760 + 9600 = 55360 B
    const int SM16 = 16 * XROW * 8 + 16 * 8 * KW * 4;   // 36608 + 7680 = 44288 B
    cudaFuncSetAttribute(gconv_kernel<20>,
                         cudaFuncAttributeMaxDynamicSharedMemorySize, SM20);
    cudaFuncSetAttribute(gconv_kernel<16>,
                         cudaFuncAttributeMaxDynamicSharedMemorySize, SM16);

    dim3 blk(NTHR);
    const int GT = T_LEN / TILE;   // 16 t-tiles
    const int BP = B_SZ / 2;       // 8 batch pairs

    // leaf: x[0:1280] -> bufA (512 ch)
    gconv_kernel<20><<<dim3(GT, 64, BP), blk, SM20>>>(
        x, 1536, 20, x, 0, 0, W_leaf, b_leaf, bufA, 512);
    // int0: bufA (512) -> bufB (256)
    gconv_kernel<16><<<dim3(GT, 32, BP), blk, SM16>>>(
        bufA, 512, 16, x, 0, 0, W_int0, b_int0, bufB, 256);
    // br: concat(bufB group 8ch, x[1280+g*8 .. +8]) -> bufA (256)
    gconv_kernel<16><<<dim3(GT, 32, BP), blk, SM16>>>(
        bufB, 256, 8, x, 1536, 1280, W_br, b_br, bufA, 256);
    // int1: bufA (256) -> bufB (128)
    gconv_kernel<16><<<dim3(GT, 16, BP), blk, SM16>>>(
        bufA, 256, 16, x, 0, 0, W_int1, b_int1, bufB, 128);
    // int2: bufB (128) -> bufA (64)
    gconv_kernel<16><<<dim3(GT, 8, BP), blk, SM16>>>(
        bufB, 128, 16, x, 0, 0, W_int2, b_int2, bufA, 64);
    // int3: bufA (64) -> bufB (32)
    gconv_kernel<16><<<dim3(GT, 4, BP), blk, SM16>>>(
        bufA, 64, 16, x, 0, 0, W_int3, b_int3, bufB, 32);
    // int4: bufB (32) -> bufA (16)
    gconv_kernel<16><<<dim3(GT, 2, BP), blk, SM16>>>(
        bufB, 32, 16, x, 0, 0, W_int4, b_int4, bufA, 16);
    // root: bufA (16) -> out
    root_kernel<<<(B_SZ * (T_LEN / 4) + 255) / 256, 256>>>(
        bufA, W_root, b_root, (float*)d_out);
}

// round 17
// speedup vs baseline: 1.1704x; 1.0005x over previous
#include <cuda_runtime.h>
#include <cstddef>

typedef unsigned long long u64;

#define T_LEN 4096
#define KW    15
#define PAD   7
#define TILE  256
#define RPT   16          // t-values per thread
#define LANES 16          // TILE / RPT
#define NTHR  128         // 8 out-channels * 16 lane-slots
#define XROW  286         // skewed row length: skew(269)=285 -> 286
#define B_SZ  16

// Scratch (alloc-guard-safe): ping-pong intermediates.
__device__ float g_bufA[(size_t)16 * 512 * 4096];   // 134 MB
__device__ float g_bufB[(size_t)16 * 256 * 4096];   //  67 MB

__device__ __forceinline__ u64 pack2(float x, float y) {
    u64 u; asm("mov.b64 %0, {%1, %2};" : "=l"(u) : "f"(x), "f"(y)); return u;
}
__device__ __forceinline__ void unpack2(u64 u, float& x, float& y) {
    asm("mov.b64 {%0, %1}, %2;" : "=f"(x), "=f"(y) : "l"(u));
}
// Packed dual-FP32 FMA (sm_100+): d = a*b + c on both 32-bit halves.
__device__ __forceinline__ u64 ffma2(u64 a, u64 b, u64 c) {
    u64 d; asm("fma.rn.f32x2 %0, %1, %2, %3;" : "=l"(d) : "l"(a), "l"(b), "l"(c));
    return d;
}
__device__ __forceinline__ float lrelu(float v) { return v > 0.f ? v : 0.01f * v; }

// Grouped 1D conv, K=15, SAME, leaky-ReLU epilogue.
// Block = (t-tile of 256) x (one group) x (one batch PAIR).
// f32x2 lanes carry batches (b0,b1).  cin0 channels come from in0 at group
// base g*cin0; the remaining CIN-cin0 channels come from in1 at channel
// in1_chbase + g*(CIN-cin0) (used only by the 'br' concat layer).
template<int CIN>
__global__ void __launch_bounds__(NTHR)
gconv_kernel(const float* __restrict__ in0, int in0_nch, int cin0,
             const float* __restrict__ in1, int in1_nch, int in1_chbase,
             const float* __restrict__ W, const float* __restrict__ bias,
             float* __restrict__ out, int out_nch)
{
    extern __shared__ u64 smem[];
    u64*   xs  = smem;                           // [CIN][XROW] skewed {b0,b1} pairs
    float* wsh = (float*)(smem + CIN * XROW);    // [8][CIN][KW] plain f32

    const int tid    = threadIdx.x;
    const int g      = blockIdx.y;
    const int tstart = blockIdx.x * TILE;
    const int b0     = blockIdx.z * 2, b1 = b0 + 1;
    const int cin1   = CIN - cin0;

    // ---- stage input tile (with halo) into skewed shared memory ----
    for (int ci = 0; ci < CIN; ++ci) {
        const float *s0, *s1;
        if (ci < cin0) {
            size_t ch = (size_t)g * cin0 + ci;
            s0 = in0 + ((size_t)b0 * in0_nch + ch) * T_LEN;
            s1 = in0 + ((size_t)b1 * in0_nch + ch) * T_LEN;
        } else {
            size_t ch = (size_t)in1_chbase + (size_t)g * cin1 + (ci - cin0);
            s0 = in1 + ((size_t)b0 * in1_nch + ch) * T_LEN;
            s1 = in1 + ((size_t)b1 * in1_nch + ch) * T_LEN;
        }
        for (int tt = tid; tt < TILE + KW - 1; tt += NTHR) {
            int t = tstart - PAD + tt;
            float vx = 0.f, vy = 0.f;
            if ((unsigned)t < (unsigned)T_LEN) { vx = s0[t]; vy = s1[t]; }
            // additive skew: conflict-free LDS.64 for lane stride of 16 pairs
            xs[ci * XROW + tt + (tt >> 4)] = pack2(vx, vy);
        }
    }
    // ---- stage this group's weights (plain f32, packed at use) ----
    {
        const float* Wg = W + (size_t)g * 8 * CIN * KW;
        for (int i = tid; i < 8 * CIN * KW; i += NTHR)
            wsh[i] = Wg[i];
    }
    __syncthreads();

    const int l  = tid & (LANES - 1);   // t-slot
    const int co = tid >> 4;            // out channel within group
    const int oc = g * 8 + co;

    const float bv = bias[oc];
    const u64 bb = pack2(bv, bv);
    u64 acc[RPT];
    #pragma unroll
    for (int r = 0; r < RPT; ++r) acc[r] = bb;

    const u64*   xbase = xs + 17 * l;        // skew(16*l + j) = 17*l + j + (j>>4)
    const float* wbase = wsh + co * CIN * KW;

    #pragma unroll 1
    for (int ci = 0; ci < CIN; ++ci) {
        const u64* xr = xbase + ci * XROW;
        u64 xv[RPT + KW - 1];                 // 30 pairs, register-resident
        #pragma unroll
        for (int j = 0; j < RPT + KW - 1; ++j) xv[j] = xr[j + (j >> 4)];
        const float* wr = wbase + ci * KW;
        #pragma unroll
        for (int k = 0; k < KW; ++k) {
            float w = wr[k];                  // broadcast LDS.32
            u64 wk = pack2(w, w);             // 1 MOV, off the fma pipe
            #pragma unroll
            for (int r = 0; r < RPT; ++r)
                acc[r] = ffma2(wk, xv[r + k], acc[r]);
        }
    }

    // ---- epilogue: leaky ReLU, unpack batch pair, vectorized store ----
    float* o0 = out + ((size_t)b0 * out_nch + oc) * T_LEN + tstart + l * RPT;
    float* o1 = out + ((size_t)b1 * out_nch + oc) * T_LEN + tstart + l * RPT;
    #pragma unroll
    for (int r4 = 0; r4 < RPT; r4 += 4) {
        float4 v0, v1; float a, b;
        unpack2(acc[r4 + 0], a, b); v0.x = lrelu(a); v1.x = lrelu(b);
        unpack2(acc[r4 + 1], a, b); v0.y = lrelu(a); v1.y = lrelu(b);
        unpack2(acc[r4 + 2], a, b); v0.z = lrelu(a); v1.z = lrelu(b);
        unpack2(acc[r4 + 3], a, b); v0.w = lrelu(a); v1.w = lrelu(b);
        *reinterpret_cast<float4*>(o0 + r4) = v0;
        *reinterpret_cast<float4*>(o1 + r4) = v1;
    }
}

// Root: 1x1 conv over 16 channels, no activation.
__global__ void root_kernel(const float* __restrict__ h,
                            const float* __restrict__ Wr,
                            const float* __restrict__ brt,
                            float* __restrict__ out)
{
    int idx = blockIdx.x * blockDim.x + threadIdx.x;   // B * T/4 threads
    if (idx >= B_SZ * (T_LEN / 4)) return;
    int b  = idx >> 10;            // T/4 = 1024
    int t4 = (idx & 1023) * 4;
    const float* hb = h + (size_t)b * 16 * T_LEN + t4;
    float bias = brt[0];
    float4 s = make_float4(bias, bias, bias, bias);
    #pragma unroll
    for (int c = 0; c < 16; ++c) {
        float w = Wr[c];
        float4 v = *reinterpret_cast<const float4*>(hb + (size_t)c * T_LEN);
        s.x += w * v.x; s.y += w * v.y; s.z += w * v.z; s.w += w * v.w;
    }
    *reinterpret_cast<float4*>(out + (size_t)b * T_LEN + t4) = s;
}

extern "C" void kernel_launch(void* const* d_in, const int* in_sizes, int n_in,
                              void* d_out, int out_size)
{
    const float* x      = (const float*)d_in[0];
    const float* W_leaf = (const float*)d_in[1];
    const float* b_leaf = (const float*)d_in[2];
    const float* W_int0 = (const float*)d_in[3];
    const float* b_int0 = (const float*)d_in[4];
    const float* W_br   = (const float*)d_in[5];
    const float* b_br   = (const float*)d_in[6];
    const float* W_int1 = (const float*)d_in[7];
    const float* b_int1 = (const float*)d_in[8];
    const float* W_int2 = (const float*)d_in[9];
    const float* b_int2 = (const float*)d_in[10];
    const float* W_int3 = (const float*)d_in[11];
    const float* b_int3 = (const float*)d_in[12];
    const float* W_int4 = (const float*)d_in[13];
    const float* b_int4 = (const float*)d_in[14];
    const float* W_root = (const float*)d_in[15];
    const float* b_root = (const float*)d_in[16];

    float *bufA = nullptr, *bufB = nullptr;
    cudaGetSymbolAddress((void**)&bufA, g_bufA);
    cudaGetSymbolAddress((void**)&bufB, g_bufB);

    const int SM20 = 20 * XROW * 8 + 20 * 8 * KW * 4;   // 45760 + 9600 = 55360 B
    const int SM16 = 16 * XROW * 8 + 16 * 8 * KW * 4;   // 36608 + 7680 = 44288 B
    cudaFuncSetAttribute(gconv_kernel<20>,
                         cudaFuncAttributeMaxDynamicSharedMemorySize, SM20);
    cudaFuncSetAttribute(gconv_kernel<16>,
                         cudaFuncAttributeMaxDynamicSharedMemorySize, SM16);

    dim3 blk(NTHR);
    const int GT = T_LEN / TILE;   // 16 t-tiles
    const int BP = B_SZ / 2;       // 8 batch pairs

    // leaf: x[0:1280] -> bufA (512 ch)
    gconv_kernel<20><<<dim3(GT, 64, BP), blk, SM20>>>(
        x, 1536, 20, x, 0, 0, W_leaf, b_leaf, bufA, 512);
    // int0: bufA (512) -> bufB (256)
    gconv_kernel<16><<<dim3(GT, 32, BP), blk, SM16>>>(
        bufA, 512, 16, x, 0, 0, W_int0, b_int0, bufB, 256);
    // br: concat(bufB group 8ch, x[1280+g*8 .. +8]) -> bufA (256)
    gconv_kernel<16><<<dim3(GT, 32, BP), blk, SM16>>>(
        bufB, 256, 8, x, 1536, 1280, W_br, b_br, bufA, 256);
    // int1: bufA (256) -> bufB (128)
    gconv_kernel<16><<<dim3(GT, 16, BP), blk, SM16>>>(
        bufA, 256, 16, x, 0, 0, W_int1, b_int1, bufB, 128);
    // int2: bufB (128) -> bufA (64)
    gconv_kernel<16><<<dim3(GT, 8, BP), blk, SM16>>>(
        bufB, 128, 16, x, 0, 0, W_int2, b_int2, bufA, 64);
    // int3: bufA (64) -> bufB (32)
    gconv_kernel<16><<<dim3(GT, 4, BP), blk, SM16>>>(
        bufA, 64, 16, x, 0, 0, W_int3, b_int3, bufB, 32);
    // int4: bufB (32) -> bufA (16)
    gconv_kernel<16><<<dim3(GT, 2, BP), blk, SM16>>>(
        bufB, 32, 16, x, 0, 0, W_int4, b_int4, bufA, 16);
    // root: bufA (16) -> out
    root_kernel<<<(B_SZ * (T_LEN / 4) + 255) / 256, 256>>>(
        bufA, W_root, b_root, (float*)d_out);
}